// round 14
// baseline (speedup 1.0000x reference)
#include <cuda_runtime.h>
#include <cuda_bf16.h>
#include <cstdint>
#include <cstddef>

#define TPB 256

// fixed problem shape upper bounds (N=4096, D=512, F=16384)
#define MAXN 4096
#define MAXD 512
#define MAXF 16384
#define NCAND_MAX 128
#define EQCAP 1024

// ---------------- static device scratch (no allocations allowed) ----------------
__device__ __nv_bfloat16 g_Abf[(size_t)MAXN * MAXD];          // x - b_dec, bf16
__device__ __nv_bfloat16 g_Wbf[(size_t)MAXF * MAXD];          // W_enc, bf16
__device__ __nv_bfloat16 g_screen[(size_t)MAXN * MAXF];       // screened scores, bf16
__device__ int   g_cand[(size_t)MAXN * NCAND_MAX];
__device__ int   g_candn[MAXN];
__device__ int   g_win_idx[MAXN * 64];
__device__ float g_win_val[MAXN * 64];
__device__ float g_row_sq[MAXN];
__device__ int   g_defK[1] = {32};

// monotonic float->uint key: larger float => larger key
__device__ __forceinline__ unsigned fkey(float f) {
    unsigned u = __float_as_uint(f);
    return (u & 0x80000000u) ? ~u : (u | 0x80000000u);
}
__device__ __forceinline__ int clampK(int K) {
    if (K > 64) K = 64; if (K < 1) K = 1; return K;
}
__device__ __forceinline__ int ncand_of(int K) {
    int nc = 2 * K; if (nc < 64) nc = 64; if (nc > NCAND_MAX) nc = NCAND_MAX; return nc;
}

// ---------------- PTX helpers (portable: sm_80+ features only; NO tcgen05 — the
// harness builds via compute_103 virtual target which lacks arch-specific insts) ----
__device__ __forceinline__ void ldsm4(uint32_t& r0, uint32_t& r1, uint32_t& r2, uint32_t& r3,
                                      const void* p) {
    uint32_t a = (uint32_t)__cvta_generic_to_shared(p);
    asm volatile("ldmatrix.sync.aligned.m8n8.x4.shared.b16 {%0,%1,%2,%3},[%4];"
                 : "=r"(r0), "=r"(r1), "=r"(r2), "=r"(r3) : "r"(a));
}
__device__ __forceinline__ void mma16816(float c[4],
                                         uint32_t a0, uint32_t a1, uint32_t a2, uint32_t a3,
                                         uint32_t b0, uint32_t b1) {
    asm volatile("mma.sync.aligned.m16n8k16.row.col.f32.bf16.bf16.f32 "
                 "{%0,%1,%2,%3},{%4,%5,%6,%7},{%8,%9},{%0,%1,%2,%3};"
                 : "+f"(c[0]), "+f"(c[1]), "+f"(c[2]), "+f"(c[3])
                 : "r"(a0), "r"(a1), "r"(a2), "r"(a3), "r"(b0), "r"(b1));
}
__device__ __forceinline__ void cp16(void* smem_dst, const void* gmem_src) {
    uint32_t a = (uint32_t)__cvta_generic_to_shared(smem_dst);
    asm volatile("cp.async.cg.shared.global [%0], [%1], 16;" :: "r"(a), "l"(gmem_src));
}
#define CP_COMMIT() asm volatile("cp.async.commit_group;" ::: "memory")
#define CP_WAIT(n)  asm volatile("cp.async.wait_group %0;" :: "n"(n) : "memory")

// =================================================================================
// K0a: W_enc -> bf16 (vectorized)
// =================================================================================
__global__ void prep_w(const float* __restrict__ W, __nv_bfloat16* __restrict__ Wb, size_t n4)
{
    size_t i = (size_t)blockIdx.x * blockDim.x + threadIdx.x;
    size_t stride = (size_t)gridDim.x * blockDim.x;
    for (; i < n4; i += stride) {
        float4 v = ((const float4*)W)[i];
        __nv_bfloat162 lo = __floats2bfloat162_rn(v.x, v.y);
        __nv_bfloat162 hi = __floats2bfloat162_rn(v.z, v.w);
        ((uint2*)Wb)[i] = make_uint2(*(uint32_t*)&lo, *(uint32_t*)&hi);
    }
}
// K0b: (x - b_dec) -> bf16
__global__ void prep_x(const float* __restrict__ x, const float* __restrict__ b_dec,
                       __nv_bfloat16* __restrict__ Ab, int N, int D)
{
    size_t n4 = ((size_t)N * D) >> 2;
    int D4 = D >> 2;
    size_t i = (size_t)blockIdx.x * blockDim.x + threadIdx.x;
    size_t stride = (size_t)gridDim.x * blockDim.x;
    for (; i < n4; i += stride) {
        float4 v = ((const float4*)x)[i];
        float4 b = ((const float4*)b_dec)[i % D4];
        __nv_bfloat162 lo = __floats2bfloat162_rn(v.x - b.x, v.y - b.y);
        __nv_bfloat162 hi = __floats2bfloat162_rn(v.z - b.z, v.w - b.w);
        ((uint2*)Ab)[i] = make_uint2(*(uint32_t*)&lo, *(uint32_t*)&hi);
    }
}

// =================================================================================
// K1: screening GEMM (bf16 mma.sync, fp32 accum), cp.async 2-stage pipeline,
//     2 CTAs/SM for latency hiding (proven in R11-R13):
//     screen = (x-b_dec)_bf16 @ W_enc_bf16^T + b_enc, stored bf16 [N,F]
// NEW (R14): epilogue also zero-fills the matching acts[N,F] tile — the GEMM is
// compute-bound with DRAM nearly idle, so these 268 MB of stores ride for free,
// and cand_topk loses its biggest traffic component.
// BM=BN=128, BK=32, 256 thr = 8 warps (2m x 4n), warp tile 64x32, mma m16n8k16
// smem rows padded to 40 bf16 (80B, 16B-aligned stride) -> conflict-free ldmatrix
// =================================================================================
__global__ __launch_bounds__(256, 2)
void gemm_screen(const __nv_bfloat16* __restrict__ A, const __nv_bfloat16* __restrict__ Bw,
                 const float* __restrict__ b_enc, __nv_bfloat16* __restrict__ Cs,
                 float* __restrict__ acts, int N, int D, int F)
{
    __shared__ __align__(16) __nv_bfloat16 As[2][128 * 40];
    __shared__ __align__(16) __nv_bfloat16 Bs[2][128 * 40];
    __shared__ float benc_s[128];

    const int tid = threadIdx.x;
    const int m0 = blockIdx.y * 128, n0 = blockIdx.x * 128;
    if (tid < 128) benc_s[tid] = b_enc[n0 + tid];

    const int warp = tid >> 5, lane = tid & 31;
    const int wm = warp & 1, wn = warp >> 1;

    const int lrow = tid >> 2;           // 0..63
    const int lq   = (tid & 3) * 8;      // bf16 col: 0,8,16,24

    const __nv_bfloat16* Ag0 = A  + (size_t)(m0 + lrow) * D + lq;
    const __nv_bfloat16* Ag1 = A  + (size_t)(m0 + lrow + 64) * D + lq;
    const __nv_bfloat16* Bg0 = Bw + (size_t)(n0 + lrow) * D + lq;
    const __nv_bfloat16* Bg1 = Bw + (size_t)(n0 + lrow + 64) * D + lq;

    float acc[4][4][4];
    #pragma unroll
    for (int mi = 0; mi < 4; ++mi)
        #pragma unroll
        for (int ni = 0; ni < 4; ++ni)
            #pragma unroll
            for (int t = 0; t < 4; ++t) acc[mi][ni][t] = 0.f;

    const int arow_base = wm * 64 + (lane & 7) + ((lane & 8) ? 8 : 0);
    const int acol_base = (lane & 16) ? 8 : 0;
    const int brow_base = wn * 32 + (lane & 7) + ((lane & 16) ? 8 : 0);
    const int bcol_base = (lane & 8) ? 8 : 0;

    const int nt = D >> 5;   // K tiles of 32

    // pipeline prologue: stage 0
    {
        cp16(&As[0][lrow * 40 + lq],        Ag0);
        cp16(&As[0][(lrow + 64) * 40 + lq], Ag1);
        cp16(&Bs[0][lrow * 40 + lq],        Bg0);
        cp16(&Bs[0][(lrow + 64) * 40 + lq], Bg1);
        CP_COMMIT();
    }

    for (int t = 0; t < nt; ++t) {
        const bool more = (t + 1 < nt);
        if (more) {
            const int kk = (t + 1) << 5;
            const int nb = (t + 1) & 1;
            cp16(&As[nb][lrow * 40 + lq],        Ag0 + kk);
            cp16(&As[nb][(lrow + 64) * 40 + lq], Ag1 + kk);
            cp16(&Bs[nb][lrow * 40 + lq],        Bg0 + kk);
            cp16(&Bs[nb][(lrow + 64) * 40 + lq], Bg1 + kk);
            CP_COMMIT();
            CP_WAIT(1);
        } else {
            CP_WAIT(0);
        }
        __syncthreads();

        const __nv_bfloat16* Ab = As[t & 1];
        const __nv_bfloat16* Bb = Bs[t & 1];

        #pragma unroll
        for (int ks = 0; ks < 2; ++ks) {
            uint32_t af[4][4];
            const int acol = ks * 16 + acol_base;
            #pragma unroll
            for (int mi = 0; mi < 4; ++mi)
                ldsm4(af[mi][0], af[mi][1], af[mi][2], af[mi][3],
                      Ab + (arow_base + mi * 16) * 40 + acol);

            uint32_t bfr[4][2];
            const int bcol = ks * 16 + bcol_base;
            #pragma unroll
            for (int nj = 0; nj < 2; ++nj) {
                uint32_t r0, r1, r2, r3;
                ldsm4(r0, r1, r2, r3, Bb + (brow_base + nj * 16) * 40 + bcol);
                bfr[nj * 2][0] = r0; bfr[nj * 2][1] = r1;
                bfr[nj * 2 + 1][0] = r2; bfr[nj * 2 + 1][1] = r3;
            }

            #pragma unroll
            for (int mi = 0; mi < 4; ++mi)
                #pragma unroll
                for (int ni = 0; ni < 4; ++ni)
                    mma16816(acc[mi][ni], af[mi][0], af[mi][1], af[mi][2], af[mi][3],
                             bfr[ni][0], bfr[ni][1]);
        }
        __syncthreads();   // buffer t&1 free for prefetch at iter t+1
    }

    // epilogue: + b_enc, convert bf16, store screen (4B stores, aligned) AND
    // zero-fill the same acts tile (scalar stores: acts is at an odd-float offset)
    #pragma unroll
    for (int mi = 0; mi < 4; ++mi) {
        const int gm = m0 + wm * 64 + mi * 16 + (lane >> 2);
        #pragma unroll
        for (int ni = 0; ni < 4; ++ni) {
            const int ln = wn * 32 + ni * 8 + (lane & 3) * 2;
            const float be0 = benc_s[ln], be1 = benc_s[ln + 1];
            __nv_bfloat162 h0 = __floats2bfloat162_rn(acc[mi][ni][0] + be0, acc[mi][ni][1] + be1);
            __nv_bfloat162 h1 = __floats2bfloat162_rn(acc[mi][ni][2] + be0, acc[mi][ni][3] + be1);
            *(__nv_bfloat162*)(Cs + (size_t)gm * F + n0 + ln)       = h0;
            *(__nv_bfloat162*)(Cs + (size_t)(gm + 8) * F + n0 + ln) = h1;
            float* a0 = acts + (size_t)gm * F + n0 + ln;
            float* a1 = acts + (size_t)(gm + 8) * F + n0 + ln;
            a0[0] = 0.f; a0[1] = 0.f;
            a1[0] = 0.f; a1[1] = 0.f;
        }
    }
}

// =================================================================================
// K2: per-row candidate selection on bf16 screened scores — smem keys, TWO full
// key passes, PLAIN smem atomics (R13-proven):
//   pass A: load gmem -> transform -> store key to smem + atomicAdd(hist[highbyte])
//   pass B: emit highbyte>d1 directly (all candidates, count < ncand), compact
//           highbyte==d1 survivors into a small capped eqlist.
// Low-byte threshold + final emit run on the tiny eqlist (~tens-hundreds entries).
// Emission is UNORDERED — rescore re-ranks exactly; ties at the screen threshold
// are far below the exact top-K boundary.
// (R14: acts zero-fill moved into the GEMM epilogue.)
// =================================================================================
__global__ __launch_bounds__(256)
void cand_topk(const __nv_bfloat16* __restrict__ S, const int* __restrict__ pK, int F)
{
    __shared__ unsigned short keys[MAXF];     // 32 KB
    __shared__ unsigned hist[256];            // 1 KB
    __shared__ unsigned eqlist[EQCAP];        // 4 KB, packed (idx<<8)|lowbyte
    __shared__ int misc[6];  // [0]=digit [1]=gt [2]=cand cnt [3]=eq cnt [4]=eq taken

    const int row = blockIdx.x;
    const int tid = threadIdx.x;
    const int ncand = ncand_of(clampK(*pK));
    const size_t rowoff = (size_t)row * F;

    hist[tid] = 0u;
    if (tid < 6) misc[tid] = 0;
    __syncthreads();

    // ---- pass A: load + transform + store + fused L1 histogram (plain atomics) ----
    const uint32_t* rp = (const uint32_t*)(S + rowoff);
    uint32_t* kp = (uint32_t*)keys;
    for (int i = tid; i < (F >> 1); i += TPB) {       // F/2 % TPB == 0: uniform trips
        uint32_t v = rp[i];
        uint32_t s = (v >> 15) & 0x00010001u;
        uint32_t k = v ^ (s * 0x7FFFu) ^ 0x80008000u;
        kp[i] = k;
        atomicAdd(&hist[(k >> 8) & 0xFFu], 1u);
        atomicAdd(&hist[k >> 24], 1u);
    }
    __syncthreads();

    // ---- L1 suffix scan + threshold bin ----
    for (int off = 1; off < 256; off <<= 1) {
        unsigned v = hist[tid];
        if (tid + off < 256) v += hist[tid + off];
        __syncthreads();
        hist[tid] = v;
        __syncthreads();
    }
    {
        unsigned ge = hist[tid];
        unsigned gt = (tid == 255) ? 0u : hist[tid + 1];
        if ((int)ge >= ncand && (int)gt < ncand) { misc[0] = tid; misc[1] = (int)gt; }
    }
    __syncthreads();
    const unsigned d1 = (unsigned)misc[0];
    const int need = ncand - misc[1];   // how many to take from bin d1 (>= 1)
    __syncthreads();

    // ---- pass B: emit hb>d1, compact hb==d1 ----
    for (int i = tid; i < (F >> 1); i += TPB) {
        uint32_t k = kp[i];
        unsigned k0 = k & 0xFFFFu, hb0 = k0 >> 8;
        if (hb0 > d1) {
            int p = atomicAdd(&misc[2], 1);
            g_cand[(size_t)row * NCAND_MAX + p] = 2 * i;
        } else if (hb0 == d1) {
            int e = atomicAdd(&misc[3], 1);
            if (e < EQCAP) eqlist[e] = ((unsigned)(2 * i) << 8) | (k0 & 0xFFu);
        }
        unsigned k1 = k >> 16, hb1 = k1 >> 8;
        if (hb1 > d1) {
            int p = atomicAdd(&misc[2], 1);
            g_cand[(size_t)row * NCAND_MAX + p] = 2 * i + 1;
        } else if (hb1 == d1) {
            int e = atomicAdd(&misc[3], 1);
            if (e < EQCAP) eqlist[e] = ((unsigned)(2 * i + 1) << 8) | (k1 & 0xFFu);
        }
    }
    __syncthreads();
    int cnt2 = misc[3]; if (cnt2 > EQCAP) cnt2 = EQCAP;

    // ---- L2 histogram over the small eqlist ----
    hist[tid] = 0u;
    __syncthreads();
    for (int i = tid; i < cnt2; i += TPB) atomicAdd(&hist[eqlist[i] & 0xFFu], 1u);
    __syncthreads();
    for (int off = 1; off < 256; off <<= 1) {
        unsigned v = hist[tid];
        if (tid + off < 256) v += hist[tid + off];
        __syncthreads();
        hist[tid] = v;
        __syncthreads();
    }
    {
        unsigned ge = hist[tid];
        unsigned gt = (tid == 255) ? 0u : hist[tid + 1];
        if ((int)ge >= need && (int)gt < need) { misc[0] = tid; misc[1] = (int)gt; }
    }
    __syncthreads();
    const unsigned t2 = (unsigned)misc[0];
    const int eq_take = need - misc[1];   // #(==t2) members to take (arbitrary subset)

    // ---- final emit from eqlist ----
    for (int i = tid; i < cnt2; i += TPB) {
        unsigned e = eqlist[i];
        unsigned lb = e & 0xFFu;
        int idx = (int)(e >> 8);
        if (lb > t2) {
            int p = atomicAdd(&misc[2], 1);
            g_cand[(size_t)row * NCAND_MAX + p] = idx;
        } else if (lb == t2) {
            int q = atomicAdd(&misc[4], 1);
            if (q < eq_take) {
                int p = atomicAdd(&misc[2], 1);
                g_cand[(size_t)row * NCAND_MAX + p] = idx;
            }
        }
    }
    __syncthreads();
    if (tid == 0) g_candn[row] = misc[2];
}

// =================================================================================
// K3: exact fp32 rescore of candidates + exact top-K ranking (ties: lowest index)
//     scatters winners into acts, records (idx,val) for decoder.
// =================================================================================
__global__ __launch_bounds__(256)
void rescore(const float* __restrict__ x, const float* __restrict__ W,
             const float* __restrict__ b_enc, const float* __restrict__ b_dec,
             const int* __restrict__ pK, float* __restrict__ acts, int D, int F)
{
    __shared__ float4 xc[MAXD / 4];
    __shared__ float sc[NCAND_MAX];
    __shared__ int   ci[NCAND_MAX];

    const int row = blockIdx.x;
    const int tid = threadIdx.x;
    const int K = clampK(*pK);
    const int tot = g_candn[row];
    const int D4 = D >> 2;

    for (int i = tid; i < D4; i += TPB) {
        float4 xv = ((const float4*)(x + (size_t)row * D))[i];
        float4 bv = ((const float4*)b_dec)[i];
        xc[i] = make_float4(xv.x - bv.x, xv.y - bv.y, xv.z - bv.z, xv.w - bv.w);
    }
    __syncthreads();

    const int warp = tid >> 5, lane = tid & 31;
    for (int c = warp; c < tot; c += 8) {
        const int f = g_cand[(size_t)row * NCAND_MAX + c];
        const float4* wr = (const float4*)(W + (size_t)f * D);
        float s = 0.f;
        for (int j = lane; j < D4; j += 32) {
            float4 w = wr[j]; float4 xv = xc[j];
            s = fmaf(xv.x, w.x, s); s = fmaf(xv.y, w.y, s);
            s = fmaf(xv.z, w.z, s); s = fmaf(xv.w, w.w, s);
        }
        #pragma unroll
        for (int off = 16; off > 0; off >>= 1)
            s += __shfl_down_sync(0xffffffffu, s, off);
        if (lane == 0) { sc[c] = s + b_enc[f]; ci[c] = f; }
    }
    __syncthreads();

    // exact ranking: rank = #{j beats i}; beats = (>) or (== && lower idx)
    for (int c = tid; c < tot; c += TPB) {
        const unsigned ki = fkey(sc[c]);
        const int idi = ci[c];
        int rank = 0;
        for (int j = 0; j < tot; ++j) {
            unsigned kj = fkey(sc[j]);
            rank += (kj > ki) || (kj == ki && ci[j] < idi);
        }
        if (rank < K) {
            g_win_idx[(row << 6) + rank] = idi;
            g_win_val[(row << 6) + rank] = sc[c];
            acts[(size_t)row * F + idi] = sc[c];
        }
    }
}

// =================================================================================
// K4: sparse decoder + per-row squared error (blockDim = D/4, float4 gathers)
// =================================================================================
__global__ void decoder_kernel(const float* __restrict__ x, const float* __restrict__ Wd,
                               const float* __restrict__ b_dec, const int* __restrict__ pK,
                               float* __restrict__ recon, int D)
{
    __shared__ int   wi[64];
    __shared__ float wv[64];
    __shared__ float red[MAXD / 4];
    const int row = blockIdx.x, tid = threadIdx.x;
    const int K = clampK(*pK);
    const int nthr = blockDim.x;                 // = D/4
    if (tid < K) { wi[tid] = g_win_idx[(row << 6) + tid]; wv[tid] = g_win_val[(row << 6) + tid]; }
    __syncthreads();

    float4 acc = ((const float4*)b_dec)[tid];
    #pragma unroll 4
    for (int j = 0; j < K; ++j) {
        float4 w = ((const float4*)(Wd + (size_t)wi[j] * D))[tid];
        const float v = wv[j];
        acc.x = fmaf(v, w.x, acc.x); acc.y = fmaf(v, w.y, acc.y);
        acc.z = fmaf(v, w.z, acc.z); acc.w = fmaf(v, w.w, acc.w);
    }
    float4 xv = ((const float4*)(x + (size_t)row * D))[tid];
    float* rr = recon + (size_t)row * D + tid * 4;    // recon base misaligned: scalar stores
    rr[0] = acc.x; rr[1] = acc.y; rr[2] = acc.z; rr[3] = acc.w;
    float dx = acc.x - xv.x, dy = acc.y - xv.y, dz = acc.z - xv.z, dw = acc.w - xv.w;
    float sq = dx * dx + dy * dy + dz * dz + dw * dw;

    red[tid] = sq;
    __syncthreads();
    for (int s = nthr / 2; s > 0; s >>= 1) {
        if (tid < s) red[tid] += red[tid + s];
        __syncthreads();
    }
    if (tid == 0) g_row_sq[row] = red[0];
}

// =================================================================================
// K5: loss = mean(row_sq)
// =================================================================================
__global__ void loss_kernel(float* __restrict__ out, int N)
{
    __shared__ float red[TPB];
    const int tid = threadIdx.x;
    float s = 0.f;
    for (int i = tid; i < N; i += TPB) s += g_row_sq[i];
    red[tid] = s;
    __syncthreads();
    for (int o = TPB / 2; o > 0; o >>= 1) {
        if (tid < o) red[tid] += red[tid + o];
        __syncthreads();
    }
    if (tid == 0) out[0] = red[0] / (float)N;
}

// =================================================================================
// launch: out = [loss(1), recon(N*D), acts(N*F)]
// =================================================================================
extern "C" void kernel_launch(void* const* d_in, const int* in_sizes, int n_in,
                              void* d_out, int out_size)
{
    const float* x   = (const float*)d_in[0];
    const float* W_e = (const float*)d_in[1];
    const float* W_d = (const float*)d_in[2];
    const float* b_e = (const float*)d_in[3];
    const float* b_d = (const float*)d_in[4];

    const int* pK;
    if (n_in >= 6) {
        pK = (const int*)d_in[5];
    } else {
        void* p = nullptr;
        cudaGetSymbolAddress(&p, g_defK);
        pK = (const int*)p;
    }

    const int D = in_sizes[4];
    const int F = in_sizes[3];
    const int N = in_sizes[0] / D;

    float* out   = (float*)d_out;
    float* recon = out + 1;
    float* acts  = out + 1 + (size_t)N * D;

    __nv_bfloat16 *Abf, *Wbf, *Scr;
    { void* p; cudaGetSymbolAddress(&p, g_Abf);    Abf = (__nv_bfloat16*)p; }
    { void* p; cudaGetSymbolAddress(&p, g_Wbf);    Wbf = (__nv_bfloat16*)p; }
    { void* p; cudaGetSymbolAddress(&p, g_screen); Scr = (__nv_bfloat16*)p; }

    // K0: bf16 conversions (vectorized)
    prep_x<<<512, 256>>>(x, b_d, Abf, N, D);
    prep_w<<<2048, 256>>>(W_e, Wbf, ((size_t)F * D) >> 2);

    // K1: bf16 tensor-core screening GEMM (+ fused acts zero-fill)
    dim3 grid(F / 128, N / 128);
    gemm_screen<<<grid, TPB>>>(Abf, Wbf, b_e, Scr, acts, N, D, F);

    // K2: candidate selection, smem keys, 2-pass, plain atomics
    cand_topk<<<N, TPB>>>(Scr, pK, F);

    // K3: exact rescore + exact top-K + scatter
    rescore<<<N, TPB>>>(x, W_e, b_e, b_d, pK, acts, D, F);

    // K4: sparse decoder + row squared error
    decoder_kernel<<<N, D / 4>>>(x, W_d, b_d, pK, recon, D);

    // K5: loss
    loss_kernel<<<1, TPB>>>(out, N);
}

// round 15
// speedup vs baseline: 1.2012x; 1.2012x over previous
#include <cuda_runtime.h>
#include <cuda_bf16.h>
#include <cstdint>
#include <cstddef>

#define TPB 256

// fixed problem shape upper bounds (N=4096, D=512, F=16384)
#define MAXN 4096
#define MAXD 512
#define MAXF 16384
#define NCAND_MAX 128
#define EQCAP 1024

// ---------------- static device scratch (no allocations allowed) ----------------
__device__ __nv_bfloat16 g_Abf[(size_t)MAXN * MAXD];          // x - b_dec, bf16
__device__ __nv_bfloat16 g_Wbf[(size_t)MAXF * MAXD];          // W_enc, bf16
__device__ __nv_bfloat16 g_screen[(size_t)MAXN * MAXF];       // screened scores, bf16
__device__ int   g_cand[(size_t)MAXN * NCAND_MAX];
__device__ int   g_candn[MAXN];
__device__ int   g_win_idx[MAXN * 64];
__device__ float g_win_val[MAXN * 64];
__device__ float g_row_sq[MAXN];
__device__ int   g_defK[1] = {32};

// monotonic float->uint key: larger float => larger key
__device__ __forceinline__ unsigned fkey(float f) {
    unsigned u = __float_as_uint(f);
    return (u & 0x80000000u) ? ~u : (u | 0x80000000u);
}
__device__ __forceinline__ int clampK(int K) {
    if (K > 64) K = 64; if (K < 1) K = 1; return K;
}
__device__ __forceinline__ int ncand_of(int K) {
    int nc = 2 * K; if (nc < 64) nc = 64; if (nc > NCAND_MAX) nc = NCAND_MAX; return nc;
}
// packed bf16x2 -> two 16-bit sortable keys
__device__ __forceinline__ uint32_t key2(uint32_t v) {
    uint32_t s = (v >> 15) & 0x00010001u;
    return v ^ (s * 0x7FFFu) ^ 0x80008000u;
}

// ---------------- PTX helpers (portable: sm_80+ features only; NO tcgen05 — the
// harness builds via compute_103 virtual target which lacks arch-specific insts) ----
__device__ __forceinline__ void ldsm4(uint32_t& r0, uint32_t& r1, uint32_t& r2, uint32_t& r3,
                                      const void* p) {
    uint32_t a = (uint32_t)__cvta_generic_to_shared(p);
    asm volatile("ldmatrix.sync.aligned.m8n8.x4.shared.b16 {%0,%1,%2,%3},[%4];"
                 : "=r"(r0), "=r"(r1), "=r"(r2), "=r"(r3) : "r"(a));
}
__device__ __forceinline__ void mma16816(float c[4],
                                         uint32_t a0, uint32_t a1, uint32_t a2, uint32_t a3,
                                         uint32_t b0, uint32_t b1) {
    asm volatile("mma.sync.aligned.m16n8k16.row.col.f32.bf16.bf16.f32 "
                 "{%0,%1,%2,%3},{%4,%5,%6,%7},{%8,%9},{%0,%1,%2,%3};"
                 : "+f"(c[0]), "+f"(c[1]), "+f"(c[2]), "+f"(c[3])
                 : "r"(a0), "r"(a1), "r"(a2), "r"(a3), "r"(b0), "r"(b1));
}
__device__ __forceinline__ void cp16(void* smem_dst, const void* gmem_src) {
    uint32_t a = (uint32_t)__cvta_generic_to_shared(smem_dst);
    asm volatile("cp.async.cg.shared.global [%0], [%1], 16;" :: "r"(a), "l"(gmem_src));
}
#define CP_COMMIT() asm volatile("cp.async.commit_group;" ::: "memory")
#define CP_WAIT(n)  asm volatile("cp.async.wait_group %0;" :: "n"(n) : "memory")

// =================================================================================
// K0a: W_enc -> bf16 (vectorized)
// =================================================================================
__global__ void prep_w(const float* __restrict__ W, __nv_bfloat16* __restrict__ Wb, size_t n4)
{
    size_t i = (size_t)blockIdx.x * blockDim.x + threadIdx.x;
    size_t stride = (size_t)gridDim.x * blockDim.x;
    for (; i < n4; i += stride) {
        float4 v = ((const float4*)W)[i];
        __nv_bfloat162 lo = __floats2bfloat162_rn(v.x, v.y);
        __nv_bfloat162 hi = __floats2bfloat162_rn(v.z, v.w);
        ((uint2*)Wb)[i] = make_uint2(*(uint32_t*)&lo, *(uint32_t*)&hi);
    }
}
// K0b: (x - b_dec) -> bf16
__global__ void prep_x(const float* __restrict__ x, const float* __restrict__ b_dec,
                       __nv_bfloat16* __restrict__ Ab, int N, int D)
{
    size_t n4 = ((size_t)N * D) >> 2;
    int D4 = D >> 2;
    size_t i = (size_t)blockIdx.x * blockDim.x + threadIdx.x;
    size_t stride = (size_t)gridDim.x * blockDim.x;
    for (; i < n4; i += stride) {
        float4 v = ((const float4*)x)[i];
        float4 b = ((const float4*)b_dec)[i % D4];
        __nv_bfloat162 lo = __floats2bfloat162_rn(v.x - b.x, v.y - b.y);
        __nv_bfloat162 hi = __floats2bfloat162_rn(v.z - b.z, v.w - b.w);
        ((uint2*)Ab)[i] = make_uint2(*(uint32_t*)&lo, *(uint32_t*)&hi);
    }
}

// =================================================================================
// K1: screening GEMM (bf16 mma.sync, fp32 accum), cp.async 2-stage pipeline,
//     2 CTAs/SM — EXACT R13 version (R14's fused acts zero-fill cost ~100us of
//     uncoalesced epilogue stores; reverted per pre-registered fallback):
//     screen = (x-b_dec)_bf16 @ W_enc_bf16^T + b_enc, stored bf16 [N,F]
// BM=BN=128, BK=32, 256 thr = 8 warps (2m x 4n), warp tile 64x32, mma m16n8k16
// smem rows padded to 40 bf16 (80B, 16B-aligned stride) -> conflict-free ldmatrix
// =================================================================================
__global__ __launch_bounds__(256, 2)
void gemm_screen(const __nv_bfloat16* __restrict__ A, const __nv_bfloat16* __restrict__ Bw,
                 const float* __restrict__ b_enc, __nv_bfloat16* __restrict__ Cs,
                 int N, int D, int F)
{
    __shared__ __align__(16) __nv_bfloat16 As[2][128 * 40];
    __shared__ __align__(16) __nv_bfloat16 Bs[2][128 * 40];
    __shared__ float benc_s[128];

    const int tid = threadIdx.x;
    const int m0 = blockIdx.y * 128, n0 = blockIdx.x * 128;
    if (tid < 128) benc_s[tid] = b_enc[n0 + tid];

    const int warp = tid >> 5, lane = tid & 31;
    const int wm = warp & 1, wn = warp >> 1;

    const int lrow = tid >> 2;           // 0..63
    const int lq   = (tid & 3) * 8;      // bf16 col: 0,8,16,24

    const __nv_bfloat16* Ag0 = A  + (size_t)(m0 + lrow) * D + lq;
    const __nv_bfloat16* Ag1 = A  + (size_t)(m0 + lrow + 64) * D + lq;
    const __nv_bfloat16* Bg0 = Bw + (size_t)(n0 + lrow) * D + lq;
    const __nv_bfloat16* Bg1 = Bw + (size_t)(n0 + lrow + 64) * D + lq;

    float acc[4][4][4];
    #pragma unroll
    for (int mi = 0; mi < 4; ++mi)
        #pragma unroll
        for (int ni = 0; ni < 4; ++ni)
            #pragma unroll
            for (int t = 0; t < 4; ++t) acc[mi][ni][t] = 0.f;

    const int arow_base = wm * 64 + (lane & 7) + ((lane & 8) ? 8 : 0);
    const int acol_base = (lane & 16) ? 8 : 0;
    const int brow_base = wn * 32 + (lane & 7) + ((lane & 16) ? 8 : 0);
    const int bcol_base = (lane & 8) ? 8 : 0;

    const int nt = D >> 5;   // K tiles of 32

    // pipeline prologue: stage 0
    {
        cp16(&As[0][lrow * 40 + lq],        Ag0);
        cp16(&As[0][(lrow + 64) * 40 + lq], Ag1);
        cp16(&Bs[0][lrow * 40 + lq],        Bg0);
        cp16(&Bs[0][(lrow + 64) * 40 + lq], Bg1);
        CP_COMMIT();
    }

    for (int t = 0; t < nt; ++t) {
        const bool more = (t + 1 < nt);
        if (more) {
            const int kk = (t + 1) << 5;
            const int nb = (t + 1) & 1;
            cp16(&As[nb][lrow * 40 + lq],        Ag0 + kk);
            cp16(&As[nb][(lrow + 64) * 40 + lq], Ag1 + kk);
            cp16(&Bs[nb][lrow * 40 + lq],        Bg0 + kk);
            cp16(&Bs[nb][(lrow + 64) * 40 + lq], Bg1 + kk);
            CP_COMMIT();
            CP_WAIT(1);
        } else {
            CP_WAIT(0);
        }
        __syncthreads();

        const __nv_bfloat16* Ab = As[t & 1];
        const __nv_bfloat16* Bb = Bs[t & 1];

        #pragma unroll
        for (int ks = 0; ks < 2; ++ks) {
            uint32_t af[4][4];
            const int acol = ks * 16 + acol_base;
            #pragma unroll
            for (int mi = 0; mi < 4; ++mi)
                ldsm4(af[mi][0], af[mi][1], af[mi][2], af[mi][3],
                      Ab + (arow_base + mi * 16) * 40 + acol);

            uint32_t bfr[4][2];
            const int bcol = ks * 16 + bcol_base;
            #pragma unroll
            for (int nj = 0; nj < 2; ++nj) {
                uint32_t r0, r1, r2, r3;
                ldsm4(r0, r1, r2, r3, Bb + (brow_base + nj * 16) * 40 + bcol);
                bfr[nj * 2][0] = r0; bfr[nj * 2][1] = r1;
                bfr[nj * 2 + 1][0] = r2; bfr[nj * 2 + 1][1] = r3;
            }

            #pragma unroll
            for (int mi = 0; mi < 4; ++mi)
                #pragma unroll
                for (int ni = 0; ni < 4; ++ni)
                    mma16816(acc[mi][ni], af[mi][0], af[mi][1], af[mi][2], af[mi][3],
                             bfr[ni][0], bfr[ni][1]);
        }
        __syncthreads();   // buffer t&1 free for prefetch at iter t+1
    }

    // epilogue: + b_enc, convert bf16, store (4B stores, screen buffer aligned)
    #pragma unroll
    for (int mi = 0; mi < 4; ++mi) {
        const int gm = m0 + wm * 64 + mi * 16 + (lane >> 2);
        #pragma unroll
        for (int ni = 0; ni < 4; ++ni) {
            const int ln = wn * 32 + ni * 8 + (lane & 3) * 2;
            const float be0 = benc_s[ln], be1 = benc_s[ln + 1];
            __nv_bfloat162 h0 = __floats2bfloat162_rn(acc[mi][ni][0] + be0, acc[mi][ni][1] + be1);
            __nv_bfloat162 h1 = __floats2bfloat162_rn(acc[mi][ni][2] + be0, acc[mi][ni][3] + be1);
            *(__nv_bfloat162*)(Cs + (size_t)gm * F + n0 + ln)       = h0;
            *(__nv_bfloat162*)(Cs + (size_t)(gm + 8) * F + n0 + ln) = h1;
        }
    }
}

// =================================================================================
// K2: per-row candidate selection — NO smem key staging (R14 ncu: 58% L1 = the
// 32KB key array write+read was the bottleneck, not gmem). Pass B re-reads the
// row from gmem instead: the whole screen array (~134MB) ~= L2 capacity, so the
// re-read is mostly L2 hits, and smem drops to ~5.3KB -> warp-limited occupancy.
//   pass A: uint4 gmem read -> transform in regs -> plain hist atomics (highbyte)
//           + vectorized acts zero-fill (R13-proven placement).
//   pass B: uint4 gmem re-read -> emit hb>d1 to g_cand, compact hb==d1 to eqlist.
// Low-byte threshold + final emit on the tiny eqlist. Emission UNORDERED —
// rescore re-ranks exactly; ties at the screen threshold are far below the exact
// top-K boundary.
// =================================================================================
__global__ __launch_bounds__(256)
void cand_topk(const __nv_bfloat16* __restrict__ S, const int* __restrict__ pK,
               float* __restrict__ acts, int F)
{
    __shared__ unsigned hist[256];            // 1 KB
    __shared__ unsigned eqlist[EQCAP];        // 4 KB, packed (idx<<8)|lowbyte
    __shared__ int misc[6];  // [0]=digit [1]=gt [2]=cand cnt [3]=eq cnt [4]=eq taken

    const int row = blockIdx.x;
    const int tid = threadIdx.x;
    const int ncand = ncand_of(clampK(*pK));
    const size_t rowoff = (size_t)row * F;

    hist[tid] = 0u;
    if (tid < 6) misc[tid] = 0;
    __syncthreads();

    // ---- pass A: vectorized read + transform + L1 histogram (plain atomics) ----
    const uint4* rp4 = (const uint4*)(S + rowoff);
    const int nq = F >> 3;                    // # of uint4 (8 bf16 each)
    for (int i = tid; i < nq; i += TPB) {
        uint4 v = rp4[i];
        uint32_t k0 = key2(v.x), k1 = key2(v.y), k2 = key2(v.z), k3 = key2(v.w);
        atomicAdd(&hist[(k0 >> 8) & 0xFFu], 1u); atomicAdd(&hist[k0 >> 24], 1u);
        atomicAdd(&hist[(k1 >> 8) & 0xFFu], 1u); atomicAdd(&hist[k1 >> 24], 1u);
        atomicAdd(&hist[(k2 >> 8) & 0xFFu], 1u); atomicAdd(&hist[k2 >> 24], 1u);
        atomicAdd(&hist[(k3 >> 8) & 0xFFu], 1u); atomicAdd(&hist[k3 >> 24], 1u);
    }

    // vectorized zero-fill of acts row (handles the odd-float global offset)
    {
        float* ar = acts + rowoff;
        size_t addr = (size_t)ar;
        int head = (int)(((16 - (addr & 15)) & 15) >> 2);
        if (head > F) head = F;
        if (tid < head) ar[tid] = 0.0f;
        const int nv = (F - head) >> 2;
        float4 z = make_float4(0.f, 0.f, 0.f, 0.f);
        float4* av = (float4*)(ar + head);
        for (int j = tid; j < nv; j += TPB) av[j] = z;
        const int tail0 = head + (nv << 2);
        if (tid < F - tail0) ar[tail0 + tid] = 0.0f;
    }
    __syncthreads();

    // ---- L1 suffix scan + threshold bin ----
    for (int off = 1; off < 256; off <<= 1) {
        unsigned v = hist[tid];
        if (tid + off < 256) v += hist[tid + off];
        __syncthreads();
        hist[tid] = v;
        __syncthreads();
    }
    {
        unsigned ge = hist[tid];
        unsigned gt = (tid == 255) ? 0u : hist[tid + 1];
        if ((int)ge >= ncand && (int)gt < ncand) { misc[0] = tid; misc[1] = (int)gt; }
    }
    __syncthreads();
    const unsigned d1 = (unsigned)misc[0];
    const int need = ncand - misc[1];   // how many to take from bin d1 (>= 1)
    __syncthreads();

    // ---- pass B: gmem re-read (L2 hits), emit hb>d1, compact hb==d1 ----
    for (int i = tid; i < nq; i += TPB) {
        uint4 v = rp4[i];
        uint32_t kk[4] = { key2(v.x), key2(v.y), key2(v.z), key2(v.w) };
        const int base = i << 3;
        #pragma unroll
        for (int w = 0; w < 4; ++w) {
            unsigned klo = kk[w] & 0xFFFFu, hlo = klo >> 8;
            if (hlo > d1) {
                int p = atomicAdd(&misc[2], 1);
                g_cand[(size_t)row * NCAND_MAX + p] = base + 2 * w;
            } else if (hlo == d1) {
                int e = atomicAdd(&misc[3], 1);
                if (e < EQCAP) eqlist[e] = ((unsigned)(base + 2 * w) << 8) | (klo & 0xFFu);
            }
            unsigned khi = kk[w] >> 16, hhi = khi >> 8;
            if (hhi > d1) {
                int p = atomicAdd(&misc[2], 1);
                g_cand[(size_t)row * NCAND_MAX + p] = base + 2 * w + 1;
            } else if (hhi == d1) {
                int e = atomicAdd(&misc[3], 1);
                if (e < EQCAP) eqlist[e] = ((unsigned)(base + 2 * w + 1) << 8) | (khi & 0xFFu);
            }
        }
    }
    __syncthreads();
    int cnt2 = misc[3]; if (cnt2 > EQCAP) cnt2 = EQCAP;

    // ---- L2 histogram over the small eqlist ----
    hist[tid] = 0u;
    __syncthreads();
    for (int i = tid; i < cnt2; i += TPB) atomicAdd(&hist[eqlist[i] & 0xFFu], 1u);
    __syncthreads();
    for (int off = 1; off < 256; off <<= 1) {
        unsigned v = hist[tid];
        if (tid + off < 256) v += hist[tid + off];
        __syncthreads();
        hist[tid] = v;
        __syncthreads();
    }
    {
        unsigned ge = hist[tid];
        unsigned gt = (tid == 255) ? 0u : hist[tid + 1];
        if ((int)ge >= need && (int)gt < need) { misc[0] = tid; misc[1] = (int)gt; }
    }
    __syncthreads();
    const unsigned t2 = (unsigned)misc[0];
    const int eq_take = need - misc[1];   // #(==t2) members to take (arbitrary subset)

    // ---- final emit from eqlist ----
    for (int i = tid; i < cnt2; i += TPB) {
        unsigned e = eqlist[i];
        unsigned lb = e & 0xFFu;
        int idx = (int)(e >> 8);
        if (lb > t2) {
            int p = atomicAdd(&misc[2], 1);
            g_cand[(size_t)row * NCAND_MAX + p] = idx;
        } else if (lb == t2) {
            int q = atomicAdd(&misc[4], 1);
            if (q < eq_take) {
                int p = atomicAdd(&misc[2], 1);
                g_cand[(size_t)row * NCAND_MAX + p] = idx;
            }
        }
    }
    __syncthreads();
    if (tid == 0) g_candn[row] = misc[2];
}

// =================================================================================
// K3: exact fp32 rescore of candidates + exact top-K ranking (ties: lowest index)
//     scatters winners into acts, records (idx,val) for decoder.
// =================================================================================
__global__ __launch_bounds__(256)
void rescore(const float* __restrict__ x, const float* __restrict__ W,
             const float* __restrict__ b_enc, const float* __restrict__ b_dec,
             const int* __restrict__ pK, float* __restrict__ acts, int D, int F)
{
    __shared__ float4 xc[MAXD / 4];
    __shared__ float sc[NCAND_MAX];
    __shared__ int   ci[NCAND_MAX];

    const int row = blockIdx.x;
    const int tid = threadIdx.x;
    const int K = clampK(*pK);
    const int tot = g_candn[row];
    const int D4 = D >> 2;

    for (int i = tid; i < D4; i += TPB) {
        float4 xv = ((const float4*)(x + (size_t)row * D))[i];
        float4 bv = ((const float4*)b_dec)[i];
        xc[i] = make_float4(xv.x - bv.x, xv.y - bv.y, xv.z - bv.z, xv.w - bv.w);
    }
    __syncthreads();

    const int warp = tid >> 5, lane = tid & 31;
    for (int c = warp; c < tot; c += 8) {
        const int f = g_cand[(size_t)row * NCAND_MAX + c];
        const float4* wr = (const float4*)(W + (size_t)f * D);
        float s = 0.f;
        for (int j = lane; j < D4; j += 32) {
            float4 w = wr[j]; float4 xv = xc[j];
            s = fmaf(xv.x, w.x, s); s = fmaf(xv.y, w.y, s);
            s = fmaf(xv.z, w.z, s); s = fmaf(xv.w, w.w, s);
        }
        #pragma unroll
        for (int off = 16; off > 0; off >>= 1)
            s += __shfl_down_sync(0xffffffffu, s, off);
        if (lane == 0) { sc[c] = s + b_enc[f]; ci[c] = f; }
    }
    __syncthreads();

    // exact ranking: rank = #{j beats i}; beats = (>) or (== && lower idx)
    for (int c = tid; c < tot; c += TPB) {
        const unsigned ki = fkey(sc[c]);
        const int idi = ci[c];
        int rank = 0;
        for (int j = 0; j < tot; ++j) {
            unsigned kj = fkey(sc[j]);
            rank += (kj > ki) || (kj == ki && ci[j] < idi);
        }
        if (rank < K) {
            g_win_idx[(row << 6) + rank] = idi;
            g_win_val[(row << 6) + rank] = sc[c];
            acts[(size_t)row * F + idi] = sc[c];
        }
    }
}

// =================================================================================
// K4: sparse decoder + per-row squared error (blockDim = D/4, float4 gathers)
// =================================================================================
__global__ void decoder_kernel(const float* __restrict__ x, const float* __restrict__ Wd,
                               const float* __restrict__ b_dec, const int* __restrict__ pK,
                               float* __restrict__ recon, int D)
{
    __shared__ int   wi[64];
    __shared__ float wv[64];
    __shared__ float red[MAXD / 4];
    const int row = blockIdx.x, tid = threadIdx.x;
    const int K = clampK(*pK);
    const int nthr = blockDim.x;                 // = D/4
    if (tid < K) { wi[tid] = g_win_idx[(row << 6) + tid]; wv[tid] = g_win_val[(row << 6) + tid]; }
    __syncthreads();

    float4 acc = ((const float4*)b_dec)[tid];
    #pragma unroll 4
    for (int j = 0; j < K; ++j) {
        float4 w = ((const float4*)(Wd + (size_t)wi[j] * D))[tid];
        const float v = wv[j];
        acc.x = fmaf(v, w.x, acc.x); acc.y = fmaf(v, w.y, acc.y);
        acc.z = fmaf(v, w.z, acc.z); acc.w = fmaf(v, w.w, acc.w);
    }
    float4 xv = ((const float4*)(x + (size_t)row * D))[tid];
    float* rr = recon + (size_t)row * D + tid * 4;    // recon base misaligned: scalar stores
    rr[0] = acc.x; rr[1] = acc.y; rr[2] = acc.z; rr[3] = acc.w;
    float dx = acc.x - xv.x, dy = acc.y - xv.y, dz = acc.z - xv.z, dw = acc.w - xv.w;
    float sq = dx * dx + dy * dy + dz * dz + dw * dw;

    red[tid] = sq;
    __syncthreads();
    for (int s = nthr / 2; s > 0; s >>= 1) {
        if (tid < s) red[tid] += red[tid + s];
        __syncthreads();
    }
    if (tid == 0) g_row_sq[row] = red[0];
}

// =================================================================================
// K5: loss = mean(row_sq)
// =================================================================================
__global__ void loss_kernel(float* __restrict__ out, int N)
{
    __shared__ float red[TPB];
    const int tid = threadIdx.x;
    float s = 0.f;
    for (int i = tid; i < N; i += TPB) s += g_row_sq[i];
    red[tid] = s;
    __syncthreads();
    for (int o = TPB / 2; o > 0; o >>= 1) {
        if (tid < o) red[tid] += red[tid + o];
        __syncthreads();
    }
    if (tid == 0) out[0] = red[0] / (float)N;
}

// =================================================================================
// launch: out = [loss(1), recon(N*D), acts(N*F)]
// =================================================================================
extern "C" void kernel_launch(void* const* d_in, const int* in_sizes, int n_in,
                              void* d_out, int out_size)
{
    const float* x   = (const float*)d_in[0];
    const float* W_e = (const float*)d_in[1];
    const float* W_d = (const float*)d_in[2];
    const float* b_e = (const float*)d_in[3];
    const float* b_d = (const float*)d_in[4];

    const int* pK;
    if (n_in >= 6) {
        pK = (const int*)d_in[5];
    } else {
        void* p = nullptr;
        cudaGetSymbolAddress(&p, g_defK);
        pK = (const int*)p;
    }

    const int D = in_sizes[4];
    const int F = in_sizes[3];
    const int N = in_sizes[0] / D;

    float* out   = (float*)d_out;
    float* recon = out + 1;
    float* acts  = out + 1 + (size_t)N * D;

    __nv_bfloat16 *Abf, *Wbf, *Scr;
    { void* p; cudaGetSymbolAddress(&p, g_Abf);    Abf = (__nv_bfloat16*)p; }
    { void* p; cudaGetSymbolAddress(&p, g_Wbf);    Wbf = (__nv_bfloat16*)p; }
    { void* p; cudaGetSymbolAddress(&p, g_screen); Scr = (__nv_bfloat16*)p; }

    // K0: bf16 conversions (vectorized)
    prep_x<<<512, 256>>>(x, b_d, Abf, N, D);
    prep_w<<<2048, 256>>>(W_e, Wbf, ((size_t)F * D) >> 2);

    // K1: bf16 tensor-core screening GEMM (R13 version, no fused stores)
    dim3 grid(F / 128, N / 128);
    gemm_screen<<<grid, TPB>>>(Abf, Wbf, b_e, Scr, N, D, F);

    // K2: candidate selection (+ acts zero-fill), no smem key staging
    cand_topk<<<N, TPB>>>(Scr, pK, acts, F);

    // K3: exact rescore + exact top-K + scatter
    rescore<<<N, TPB>>>(x, W_e, b_e, b_d, pK, acts, D, F);

    // K4: sparse decoder + row squared error
    decoder_kernel<<<N, D / 4>>>(x, W_d, b_d, pK, recon, D);

    // K5: loss
    loss_kernel<<<1, TPB>>>(out, N);
}